// round 4
// baseline (speedup 1.0000x reference)
#include <cuda_runtime.h>
#include <math.h>

#define N     16384
#define BKT   8192          // buckets (lambda = 2)
#define T     1024          // threads
#define V4PT  (N / 4 / T)   // 4 float4-groups per thread
#define BPT   (BKT / T)     // 8 buckets per thread

// dynamic smem layout (bytes):
//   W      : float[BKT]    @ 0       (32KB) bucket exp-sums -> exclusive prefix
//   A      : int[BKT]      @ 32768   (32KB) counts -> alloc cursor -> bucket ends
//   sorted : float2[N]     @ 65536   (128KB) {duration, exp(theta)} bucket-grouped
#define SMEM_BYTES (32768 + 32768 + 131072)

extern __shared__ char smem_raw[];

__device__ __forceinline__ int bucket_of(float d) {
    int b = (int)(d * (float)BKT);
    if (b >= BKT) b = BKT - 1;
    if (b < 0) b = 0;
    return b;
}

__global__ void __launch_bounds__(T, 1)
cox_fused_kernel(const float* __restrict__ theta,
                 const float* __restrict__ dur,
                 const float* __restrict__ ev,
                 float* __restrict__ out) {
    float*  W      = (float*)(smem_raw);
    int*    A      = (int*)(smem_raw + 32768);
    float2* sorted = (float2*)(smem_raw + 65536);

    __shared__ float warpTotF[32];
    __shared__ float warpPreF[32];
    __shared__ int   warpTotI[32];
    __shared__ int   warpPreI[32];
    __shared__ float s_total;

    const int t    = threadIdx.x;
    const int lane = t & 31;
    const int wid  = t >> 5;

    const float4* theta4 = (const float4*)theta;
    const float4* dur4   = (const float4*)dur;
    const float4* ev4    = (const float4*)ev;

    // ---- Phase 1: zero buckets ----
    #pragma unroll
    for (int k = 0; k < BPT; ++k) {
        int b = t + k * T;
        W[b] = 0.0f;
        A[b] = 0;
    }
    __syncthreads();

    // ---- Pass A: count + weight buckets; fold ev*theta ----
    float acc = 0.0f;
    #pragma unroll
    for (int k = 0; k < V4PT; ++k) {
        int g = t + k * T;                  // coalesced float4 index
        float4 th = theta4[g];
        float4 dd = dur4[g];
        float4 ee = ev4[g];
        acc += ee.x * th.x + ee.y * th.y + ee.z * th.z + ee.w * th.w;
        {
            int b = bucket_of(dd.x);
            atomicAdd(&W[b], __expf(th.x)); atomicAdd(&A[b], 1);
        }
        {
            int b = bucket_of(dd.y);
            atomicAdd(&W[b], __expf(th.y)); atomicAdd(&A[b], 1);
        }
        {
            int b = bucket_of(dd.z);
            atomicAdd(&W[b], __expf(th.z)); atomicAdd(&A[b], 1);
        }
        {
            int b = bucket_of(dd.w);
            atomicAdd(&W[b], __expf(th.w)); atomicAdd(&A[b], 1);
        }
    }
    __syncthreads();

    // ---- Scan: exclusive prefix of W (float) and A (int), in place ----
    float locF[BPT]; int locI[BPT];
    float runF = 0.0f; int runI = 0;
    #pragma unroll
    for (int k = 0; k < BPT; ++k) {
        locF[k] = runF;  runF += W[t * BPT + k];
        locI[k] = runI;  runI += A[t * BPT + k];
    }
    float inclF = runF; int inclI = runI;
    #pragma unroll
    for (int off = 1; off < 32; off <<= 1) {
        float vF = __shfl_up_sync(0xFFFFFFFFu, inclF, off);
        int   vI = __shfl_up_sync(0xFFFFFFFFu, inclI, off);
        if (lane >= off) { inclF += vF; inclI += vI; }
    }
    if (lane == 31) { warpTotF[wid] = inclF; warpTotI[wid] = inclI; }
    __syncthreads();
    if (wid == 0) {
        float vF = warpTotF[lane]; int vI = warpTotI[lane];
        float wF = vF; int wI = vI;
        #pragma unroll
        for (int off = 1; off < 32; off <<= 1) {
            float uF = __shfl_up_sync(0xFFFFFFFFu, wF, off);
            int   uI = __shfl_up_sync(0xFFFFFFFFu, wI, off);
            if (lane >= off) { wF += uF; wI += uI; }
        }
        warpPreF[lane] = wF - vF;
        warpPreI[lane] = wI - vI;
        if (lane == 31) s_total = wF;
    }
    __syncthreads();
    float segF = warpPreF[wid] + (inclF - runF);
    int   segI = warpPreI[wid] + (inclI - runI);
    #pragma unroll
    for (int k = 0; k < BPT; ++k) {
        W[t * BPT + k] = segF + locF[k];    // exclusive weight prefix
        A[t * BPT + k] = segI + locI[k];    // alloc cursor = bucket start
    }
    float total = s_total;
    __syncthreads();

    // ---- Pass B: scatter (d, e) into bucket-grouped array ----
    #pragma unroll
    for (int k = 0; k < V4PT; ++k) {
        int g = t + k * T;
        float4 th = theta4[g];              // L1 hits
        float4 dd = dur4[g];
        {
            int b = bucket_of(dd.x);
            int s = atomicAdd(&A[b], 1);
            sorted[s] = make_float2(dd.x, __expf(th.x));
        }
        {
            int b = bucket_of(dd.y);
            int s = atomicAdd(&A[b], 1);
            sorted[s] = make_float2(dd.y, __expf(th.y));
        }
        {
            int b = bucket_of(dd.z);
            int s = atomicAdd(&A[b], 1);
            sorted[s] = make_float2(dd.z, __expf(th.z));
        }
        {
            int b = bucket_of(dd.w);
            int s = atomicAdd(&A[b], 1);
            sorted[s] = make_float2(dd.w, __expf(th.w));
        }
    }
    __syncthreads();
    // Now A[b] = end of bucket b; start of bucket b = (b ? A[b-1] : 0).

    // ---- Phase 4: per-item risk sum (independent LDS reads) ----
    #pragma unroll
    for (int k = 0; k < V4PT; ++k) {
        int g = t + k * T;
        float4 dd = dur4[g];                // L1 hits
        float4 ee = ev4[g];
        float dv[4] = {dd.x, dd.y, dd.z, dd.w};
        float es[4] = {ee.x, ee.y, ee.z, ee.w};
        #pragma unroll
        for (int u = 0; u < 4; ++u) {
            float d = dv[u];
            int b = bucket_of(d);
            int s0 = (b == 0) ? 0 : A[b - 1];
            int s1 = A[b];
            float S = W[b];
            for (int s = s0; s < s1; ++s) {
                float2 v = sorted[s];
                if (v.x < d) S += v.y;      // strict <: self & ties excluded
            }
            float risk = total - S;         // sum over d_j >= d_i
            acc -= es[u] * __logf(risk);
        }
    }

    // ---- Phase 5: reduction -> -mean ----
    #pragma unroll
    for (int off = 16; off > 0; off >>= 1)
        acc += __shfl_down_sync(0xFFFFFFFFu, acc, off);
    __syncthreads();
    if (lane == 0) warpTotF[wid] = acc;
    __syncthreads();
    if (wid == 0) {
        float v = warpTotF[lane];
        #pragma unroll
        for (int off = 16; off > 0; off >>= 1)
            v += __shfl_down_sync(0xFFFFFFFFu, v, off);
        if (lane == 0) out[0] = -v / (float)N;
    }
}

extern "C" void kernel_launch(void* const* d_in, const int* in_sizes, int n_in,
                              void* d_out, int out_size) {
    const float* theta = (const float*)d_in[0];  // hazard_pred (N,1)
    const float* dur   = (const float*)d_in[1];  // durations (N,)
    const float* ev    = (const float*)d_in[2];  // events (N,)
    float* out = (float*)d_out;

    static int configured = 0;
    if (!configured) {
        cudaFuncSetAttribute(cox_fused_kernel,
                             cudaFuncAttributeMaxDynamicSharedMemorySize,
                             SMEM_BYTES);
        configured = 1;
    }
    cox_fused_kernel<<<1, T, SMEM_BYTES>>>(theta, dur, ev, out);
}

// round 5
// speedup vs baseline: 1.0770x; 1.0770x over previous
#include <cuda_runtime.h>
#include <math.h>

#define N     16384
#define BKT   8192          // buckets (lambda = 2)
#define NB    64            // blocks (all co-resident: 64 <= 148 SMs)
#define TPB   256           // threads per block; NB*TPB == N (1 item/thread)
#define BPB   (BKT / NB)    // 128 buckets per block

// ---- global scratch (no allocation allowed) ----
__device__ float  g_W[BKT];       // bucket exp-sums -> exclusive weight prefix
__device__ int    g_A[BKT];       // bucket counts
__device__ int    g_C[BKT];       // alloc cursors -> bucket ends
__device__ float2 g_sorted[N];    // {duration, exp(theta)} bucket-grouped
__device__ float  g_WT[NB];       // per-block weight totals
__device__ int    g_AT[NB];       // per-block count totals
__device__ float  g_acc1;         // sum ev*theta
__device__ float  g_acc2;         // sum ev*log(risk)
__device__ unsigned int g_count = 0;   // barrier arrivals
__device__ unsigned int g_sense = 0;   // barrier sense (monotonic across replays)

// Sense-reversing grid barrier. Safe across graph replays (sense never resets).
__device__ __forceinline__ void grid_barrier() {
    __syncthreads();
    if (threadIdx.x == 0) {
        __threadfence();                              // publish prior stores
        unsigned int s = atomicAdd(&g_sense, 0u);     // pre-flip sense
        if (atomicAdd(&g_count, 1u) == NB - 1) {
            atomicExch(&g_count, 0u);
            __threadfence();
            atomicExch(&g_sense, s + 1u);             // release
        } else {
            while (atomicAdd(&g_sense, 0u) == s) {}
        }
    }
    __syncthreads();
}

__device__ __forceinline__ int bucket_of(float d) {
    int b = (int)(d * (float)BKT);
    if (b >= BKT) b = BKT - 1;
    if (b < 0) b = 0;
    return b;
}

__global__ void __launch_bounds__(TPB, 1)
cox_grid_kernel(const float* __restrict__ theta,
                const float* __restrict__ dur,
                const float* __restrict__ ev,
                float* __restrict__ out) {
    const int t    = threadIdx.x;
    const int k    = blockIdx.x;
    const int g    = k * TPB + t;          // global item / index
    const int lane = t & 31;
    const int wid  = t >> 5;

    __shared__ float s_wtW[8];
    __shared__ int   s_wtC[8];
    __shared__ float s_woff, s_total;
    __shared__ int   s_coff;

    // ---- Phase 0: zero ----
    if (g < BKT) { g_W[g] = 0.0f; g_A[g] = 0; }
    else if (g == BKT) { atomicExch(&g_acc1, 0.0f); atomicExch(&g_acc2, 0.0f); }
    grid_barrier();                                            // B1

    // ---- Pass A: scatter weights + counts; fold ev*theta ----
    float th = theta[g];
    float d  = dur[g];
    float e_ = ev[g];
    float e  = __expf(th);
    int   b  = bucket_of(d);
    atomicAdd(&g_W[b], e);
    atomicAdd(&g_A[b], 1);
    {
        float v = e_ * th;
        #pragma unroll
        for (int off = 16; off > 0; off >>= 1)
            v += __shfl_down_sync(0xFFFFFFFFu, v, off);
        if (lane == 0) atomicAdd(&g_acc1, v);
    }
    grid_barrier();                                            // B2

    // ---- Local scan: block k scans buckets [128k, 128k+128) ----
    float exclW = 0.0f; int exclC = 0;
    float wv = 0.0f;    int cv = 0;
    const int base = k * BPB;
    if (t < BPB) {                         // 128 threads, 4 warps
        wv = __ldcg(&g_W[base + t]);
        cv = __ldcg(&g_A[base + t]);
        float iW = wv; int iC = cv;
        #pragma unroll
        for (int off = 1; off < 32; off <<= 1) {
            float uW = __shfl_up_sync(0xFFFFFFFFu, iW, off);
            int   uC = __shfl_up_sync(0xFFFFFFFFu, iC, off);
            if (lane >= off) { iW += uW; iC += uC; }
        }
        if (lane == 31) { s_wtW[wid] = iW; s_wtC[wid] = iC; }
        exclW = iW - wv; exclC = iC - cv;  // intra-warp exclusive
    }
    __syncthreads();
    if (t < BPB) {
        #pragma unroll
        for (int j = 0; j < 4; ++j)
            if (j < wid) { exclW += s_wtW[j]; exclC += s_wtC[j]; }
    }
    if (t == 0) {
        float bw = s_wtW[0] + s_wtW[1] + s_wtW[2] + s_wtW[3];
        int   bc = s_wtC[0] + s_wtC[1] + s_wtC[2] + s_wtC[3];
        g_WT[k] = bw; g_AT[k] = bc;
    }
    grid_barrier();                                            // B3

    // ---- Block offsets + grand total (warp 0, redundant per block) ----
    if (wid == 0) {
        float a0 = __ldcg(&g_WT[lane]);
        float a1 = __ldcg(&g_WT[lane + 32]);
        int   c0 = __ldcg(&g_AT[lane]);
        int   c1 = __ldcg(&g_AT[lane + 32]);
        float mo = (lane < k ? a0 : 0.0f) + (lane + 32 < k ? a1 : 0.0f);
        int   mc = (lane < k ? c0 : 0)    + (lane + 32 < k ? c1 : 0);
        float tt = a0 + a1;
        #pragma unroll
        for (int off = 16; off > 0; off >>= 1) {
            mo += __shfl_down_sync(0xFFFFFFFFu, mo, off);
            mc += __shfl_down_sync(0xFFFFFFFFu, mc, off);
            tt += __shfl_down_sync(0xFFFFFFFFu, tt, off);
        }
        if (lane == 0) { s_woff = mo; s_coff = mc; s_total = tt; }
    }
    __syncthreads();
    if (t < BPB) {
        g_W[base + t] = s_woff + exclW;    // exclusive weight prefix
        g_C[base + t] = s_coff + exclC;    // bucket start cursor
    }
    float total = s_total;
    grid_barrier();                                            // B4

    // ---- Pass B: scatter (d, e) into bucket-grouped array ----
    {
        int s = atomicAdd(&g_C[b], 1);
        g_sorted[s] = make_float2(d, e);
    }
    grid_barrier();                                            // B5
    // Now g_C[b] = end of bucket b; start of b = (b ? g_C[b-1] : 0).

    // ---- Phase 4: per-item risk sum ----
    {
        int s0 = (b == 0) ? 0 : __ldcg(&g_C[b - 1]);
        int s1 = __ldcg(&g_C[b]);
        float S = __ldcg(&g_W[b]);
        for (int s = s0; s < s1; ++s) {
            float2 v = __ldcg(&g_sorted[s]);
            if (v.x < d) S += v.y;         // strict <: self & ties excluded
        }
        float risk = total - S;            // sum over d_j >= d_i
        float v = e_ * __logf(risk);
        #pragma unroll
        for (int off = 16; off > 0; off >>= 1)
            v += __shfl_down_sync(0xFFFFFFFFu, v, off);
        if (lane == 0) atomicAdd(&g_acc2, v);
    }
    grid_barrier();                                            // B6

    // ---- Finalize ----
    if (g == 0) {
        float a1v = atomicAdd(&g_acc1, 0.0f);
        float a2v = atomicAdd(&g_acc2, 0.0f);
        out[0] = -(a1v - a2v) / (float)N;
    }
}

extern "C" void kernel_launch(void* const* d_in, const int* in_sizes, int n_in,
                              void* d_out, int out_size) {
    const float* theta = (const float*)d_in[0];  // hazard_pred (N,1)
    const float* dur   = (const float*)d_in[1];  // durations (N,)
    const float* ev    = (const float*)d_in[2];  // events (N,)
    float* out = (float*)d_out;

    cox_grid_kernel<<<NB, TPB>>>(theta, dur, ev, out);
}

// round 6
// speedup vs baseline: 1.0890x; 1.0111x over previous
#include <cuda_runtime.h>
#include <math.h>

#define N     16384
#define BKT   8192          // buckets (lambda = 2)
#define NB    8             // CTAs in ONE cluster (hw barrier domain)
#define TPB   1024          // threads per CTA -> 8192 threads, 2 items each
#define IPT   2
#define BPC   (BKT / NB)    // 1024 buckets per CTA segment (1 per thread)

// ---- global scratch (L2-resident; no allocation allowed) ----
__device__ float  g_W[BKT];       // bucket exp-sums -> exclusive weight prefix
__device__ int    g_A[BKT];       // bucket counts (kept for bucket-start calc)
__device__ int    g_C[BKT];       // start cursor -> end after scatter
__device__ float2 g_sorted[N];    // {duration, exp(theta)} bucket-grouped
__device__ float  g_WT[NB];       // per-CTA weight totals
__device__ int    g_AT[NB];       // per-CTA count totals
__device__ float  g_acc;          // sum ev*(theta - log(risk))

__device__ __forceinline__ void cluster_sync() {
    asm volatile("barrier.cluster.arrive.aligned;" ::: "memory");
    asm volatile("barrier.cluster.wait.aligned;" ::: "memory");
}

__device__ __forceinline__ int bucket_of(float d) {
    int b = (int)(d * (float)BKT);
    if (b >= BKT) b = BKT - 1;
    if (b < 0) b = 0;
    return b;
}

__global__ void __launch_bounds__(TPB, 1) __cluster_dims__(NB, 1, 1)
cox_cluster_kernel(const float* __restrict__ theta,
                   const float* __restrict__ dur,
                   const float* __restrict__ ev,
                   float* __restrict__ out) {
    const int t    = threadIdx.x;
    const int k    = blockIdx.x;
    const int g    = k * TPB + t;          // 0..8191: my bucket AND my item base
    const int lane = t & 31;
    const int wid  = t >> 5;               // 0..31
    const int base = k * BPC;

    __shared__ float warpTotF[32];
    __shared__ float warpPreF[32];
    __shared__ int   warpTotI[32];
    __shared__ int   warpPreI[32];
    __shared__ float s_woff, s_total;
    __shared__ int   s_coff;

    // ---- Phase 0: zero (each thread owns exactly one bucket) ----
    g_W[g] = 0.0f;
    g_A[g] = 0;
    if (g == 0) atomicExch(&g_acc, 0.0f);
    __threadfence();
    cluster_sync();                                            // B1

    // ---- Pass A: load items into regs; scatter weights + counts ----
    const int i0 = g;
    const int i1 = g + 8192;
    float th0 = theta[i0], th1 = theta[i1];
    float d0  = dur[i0],   d1  = dur[i1];
    float ev0 = ev[i0],    ev1 = ev[i1];
    float e0  = __expf(th0), e1 = __expf(th1);
    int   b0  = bucket_of(d0), b1 = bucket_of(d1);
    float acc = ev0 * th0 + ev1 * th1;
    atomicAdd(&g_W[b0], e0);  atomicAdd(&g_A[b0], 1);
    atomicAdd(&g_W[b1], e1);  atomicAdd(&g_A[b1], 1);
    __threadfence();
    cluster_sync();                                            // B2

    // ---- Scan: CTA k scans its 1024-bucket segment ----
    float wv = __ldcg(&g_W[base + t]);
    int   cv = __ldcg(&g_A[base + t]);
    float iW = wv; int iC = cv;
    #pragma unroll
    for (int off = 1; off < 32; off <<= 1) {
        float uW = __shfl_up_sync(0xFFFFFFFFu, iW, off);
        int   uC = __shfl_up_sync(0xFFFFFFFFu, iC, off);
        if (lane >= off) { iW += uW; iC += uC; }
    }
    if (lane == 31) { warpTotF[wid] = iW; warpTotI[wid] = iC; }
    __syncthreads();
    if (wid == 0) {
        float vF = warpTotF[lane]; int vI = warpTotI[lane];
        float wF = vF; int wI = vI;
        #pragma unroll
        for (int off = 1; off < 32; off <<= 1) {
            float uF = __shfl_up_sync(0xFFFFFFFFu, wF, off);
            int   uI = __shfl_up_sync(0xFFFFFFFFu, wI, off);
            if (lane >= off) { wF += uF; wI += uI; }
        }
        warpPreF[lane] = wF - vF;           // exclusive warp prefix
        warpPreI[lane] = wI - vI;
        if (lane == 31) { g_WT[k] = wF; g_AT[k] = wI; }  // CTA totals
    }
    __syncthreads();
    float exclW = warpPreF[wid] + (iW - wv);   // segment-local exclusive
    int   exclC = warpPreI[wid] + (iC - cv);
    __threadfence();
    cluster_sync();                                            // B3

    // ---- Combine: each CTA computes its offset + grand total ----
    if (wid == 0) {
        float a = (lane < NB) ? __ldcg(&g_WT[lane]) : 0.0f;
        int   c = (lane < NB) ? __ldcg(&g_AT[lane]) : 0;
        float mo = (lane < k) ? a : 0.0f;
        int   mc = (lane < k) ? c : 0;
        float tt = a;
        #pragma unroll
        for (int off = 16; off > 0; off >>= 1) {
            mo += __shfl_down_sync(0xFFFFFFFFu, mo, off);
            mc += __shfl_down_sync(0xFFFFFFFFu, mc, off);
            tt += __shfl_down_sync(0xFFFFFFFFu, tt, off);
        }
        if (lane == 0) { s_woff = mo; s_coff = mc; s_total = tt; }
    }
    __syncthreads();
    float total = s_total;
    g_W[base + t] = s_woff + exclW;        // exclusive weight prefix
    g_C[base + t] = s_coff + exclC;        // bucket start cursor
    __threadfence();
    cluster_sync();                                            // B4

    // ---- Pass B: scatter (d, e) into bucket-grouped array ----
    {
        int s = atomicAdd(&g_C[b0], 1);
        g_sorted[s] = make_float2(d0, e0);
    }
    {
        int s = atomicAdd(&g_C[b1], 1);
        g_sorted[s] = make_float2(d1, e1);
    }
    __threadfence();
    cluster_sync();                                            // B5
    // Now g_C[b] = end of bucket b; start = end - g_A[b].

    // ---- Phase 4: per-item risk sum ----
    #pragma unroll
    for (int u = 0; u < IPT; ++u) {
        float d  = (u == 0) ? d0  : d1;
        float e_ = (u == 0) ? ev0 : ev1;
        int   b  = (u == 0) ? b0  : b1;
        int s1 = __ldcg(&g_C[b]);
        int s0 = s1 - __ldcg(&g_A[b]);
        float S = __ldcg(&g_W[b]);
        for (int s = s0; s < s1; ++s) {
            float2 v = __ldcg(&g_sorted[s]);
            if (v.x < d) S += v.y;          // strict <: self & ties excluded
        }
        float risk = total - S;             // sum over d_j >= d_i
        acc -= e_ * __logf(risk);
    }

    // ---- Reduce: warp shuffle -> one atomic per warp -> B6 -> write ----
    #pragma unroll
    for (int off = 16; off > 0; off >>= 1)
        acc += __shfl_down_sync(0xFFFFFFFFu, acc, off);
    if (lane == 0) atomicAdd(&g_acc, acc);
    __threadfence();
    cluster_sync();                                            // B6
    if (g == 0) out[0] = -atomicAdd(&g_acc, 0.0f) / (float)N;
}

extern "C" void kernel_launch(void* const* d_in, const int* in_sizes, int n_in,
                              void* d_out, int out_size) {
    const float* theta = (const float*)d_in[0];  // hazard_pred (N,1)
    const float* dur   = (const float*)d_in[1];  // durations (N,)
    const float* ev    = (const float*)d_in[2];  // events (N,)
    float* out = (float*)d_out;

    cox_cluster_kernel<<<NB, TPB>>>(theta, dur, ev, out);
}

// round 8
// speedup vs baseline: 1.1810x; 1.0845x over previous
#include <cuda_runtime.h>
#include <cstdint>
#include <math.h>

#define N     16384
#define BKT   8192          // buckets (lambda = 2)
#define NB    8             // CTAs in ONE cluster
#define TPB   1024          // 8192 threads total, 2 items each
#define BPC   (BKT / NB)    // 1024 buckets owned per CTA

// ---- global scratch (L2; no allocation allowed) ----
__device__ float  g_W[BKT];       // exclusive weight prefix
__device__ int    g_S[BKT];       // bucket start (immutable copy)
__device__ int    g_C[BKT];       // cursor -> becomes bucket end
__device__ float2 g_sorted[N];    // {duration, exp(theta)} bucket-grouped
__device__ float  g_WT[NB];       // per-CTA weight totals
__device__ int    g_AT[NB];       // per-CTA count totals

// dynamic smem: W_loc float[BKT] @0 (32KB), A_loc uint[BKT] @32768 (32KB)
#define SMEM_BYTES 65536
extern __shared__ char smem_raw[];

__device__ __forceinline__ void cluster_sync() {
    // arrive = release, wait = acquire (cluster scope) -> no explicit fences
    asm volatile("barrier.cluster.arrive.aligned;" ::: "memory");
    asm volatile("barrier.cluster.wait.aligned;" ::: "memory");
}

__device__ __forceinline__ unsigned int smem_u32(const void* p) {
    unsigned int a;
    asm("{ .reg .u64 t; cvta.to.shared.u64 t, %1; cvt.u32.u64 %0, t; }"
        : "=r"(a) : "l"(p));
    return a;
}

__device__ __forceinline__ unsigned int mapa_rank(unsigned int addr,
                                                  unsigned int rank) {
    unsigned int r;
    asm("mapa.shared::cluster.u32 %0, %1, %2;" : "=r"(r) : "r"(addr), "r"(rank));
    return r;
}

__device__ __forceinline__ float ld_dsmem_f32(unsigned int addr) {
    float v;
    asm volatile("ld.shared::cluster.f32 %0, [%1];" : "=f"(v) : "r"(addr));
    return v;
}

__device__ __forceinline__ int ld_dsmem_s32(unsigned int addr) {
    int v;
    asm volatile("ld.shared::cluster.s32 %0, [%1];" : "=r"(v) : "r"(addr));
    return v;
}

__device__ __forceinline__ int bucket_of(float d) {
    int b = (int)(d * (float)BKT);
    if (b >= BKT) b = BKT - 1;
    if (b < 0) b = 0;
    return b;
}

__global__ void __launch_bounds__(TPB, 1) __cluster_dims__(NB, 1, 1)
cox_cluster_kernel(const float* __restrict__ theta,
                   const float* __restrict__ dur,
                   const float* __restrict__ ev,
                   float* __restrict__ out) {
    float*        W_loc = (float*)(smem_raw);
    unsigned int* A_loc = (unsigned int*)(smem_raw + 32768);

    __shared__ float warpTotF[32];
    __shared__ float warpPreF[32];
    __shared__ int   warpTotI[32];
    __shared__ int   warpPreI[32];
    __shared__ float s_woff, s_total;
    __shared__ int   s_coff;

    const int t    = threadIdx.x;
    const int k    = blockIdx.x;
    const int g    = k * TPB + t;
    const int lane = t & 31;
    const int wid  = t >> 5;
    const int base = k * BPC;

    // ---- Phase 0: zero LOCAL histogram (smem only, no global zero) ----
    #pragma unroll
    for (int j = 0; j < BKT / TPB; ++j) {
        W_loc[t + j * TPB] = 0.0f;
        A_loc[t + j * TPB] = 0u;
    }
    if (g == 0) out[0] = 0.0f;             // ordered before final adds by B1+
    __syncthreads();

    // ---- Pass A: local smem histogram of this CTA's 2048 items ----
    const int i0 = g;
    const int i1 = g + NB * TPB;
    float th0 = theta[i0], th1 = theta[i1];
    float d0  = dur[i0],   d1  = dur[i1];
    float ev0 = ev[i0],    ev1 = ev[i1];
    float e0  = __expf(th0), e1 = __expf(th1);
    int   b0  = bucket_of(d0), b1 = bucket_of(d1);
    float acc = ev0 * th0 + ev1 * th1;
    atomicAdd(&W_loc[b0], e0);  atomicAdd(&A_loc[b0], 1u);
    atomicAdd(&W_loc[b1], e1);  atomicAdd(&A_loc[b1], 1u);
    cluster_sync();                                            // B1

    // ---- Cross-CTA gather: owner CTA sums 8 local copies (DSMEM) ----
    const unsigned int wAddr = smem_u32(&W_loc[base + t]);
    const unsigned int aAddr = smem_u32(&A_loc[base + t]);
    float wv = 0.0f; int cv = 0;
    #pragma unroll
    for (int c = 0; c < NB; ++c) {
        wv += ld_dsmem_f32(mapa_rank(wAddr, (unsigned int)c));
        cv += ld_dsmem_s32(mapa_rank(aAddr, (unsigned int)c));
    }

    // ---- Intra-CTA scan over its 1024-bucket segment ----
    float iW = wv; int iC = cv;
    #pragma unroll
    for (int off = 1; off < 32; off <<= 1) {
        float uW = __shfl_up_sync(0xFFFFFFFFu, iW, off);
        int   uC = __shfl_up_sync(0xFFFFFFFFu, iC, off);
        if (lane >= off) { iW += uW; iC += uC; }
    }
    if (lane == 31) { warpTotF[wid] = iW; warpTotI[wid] = iC; }
    __syncthreads();
    if (wid == 0) {
        float vF = warpTotF[lane]; int vI = warpTotI[lane];
        float wF = vF; int wI = vI;
        #pragma unroll
        for (int off = 1; off < 32; off <<= 1) {
            float uF = __shfl_up_sync(0xFFFFFFFFu, wF, off);
            int   uI = __shfl_up_sync(0xFFFFFFFFu, wI, off);
            if (lane >= off) { wF += uF; wI += uI; }
        }
        warpPreF[lane] = wF - vF;
        warpPreI[lane] = wI - vI;
        if (lane == 31) { g_WT[k] = wF; g_AT[k] = wI; }  // CTA totals (plain st)
    }
    __syncthreads();
    float exclW = warpPreF[wid] + (iW - wv);
    int   exclC = warpPreI[wid] + (iC - cv);
    cluster_sync();                                            // B2

    // ---- Combine: per-CTA offsets + grand total ----
    if (wid == 0) {
        float a = (lane < NB) ? __ldcg(&g_WT[lane]) : 0.0f;
        int   c = (lane < NB) ? __ldcg(&g_AT[lane]) : 0;
        float mo = (lane < k) ? a : 0.0f;
        int   mc = (lane < k) ? c : 0;
        float tt = a;
        #pragma unroll
        for (int off = 16; off > 0; off >>= 1) {
            mo += __shfl_down_sync(0xFFFFFFFFu, mo, off);
            mc += __shfl_down_sync(0xFFFFFFFFu, mc, off);
            tt += __shfl_down_sync(0xFFFFFFFFu, tt, off);
        }
        if (lane == 0) { s_woff = mo; s_coff = mc; s_total = tt; }
    }
    __syncthreads();
    float total = s_total;
    int   start = s_coff + exclC;
    g_W[base + t] = s_woff + exclW;        // exclusive weight prefix
    g_S[base + t] = start;                 // immutable start
    g_C[base + t] = start;                 // mutable cursor
    cluster_sync();                                            // B3

    // ---- Pass B: scatter (d, e) into bucket-grouped array ----
    {
        int s = atomicAdd(&g_C[b0], 1);
        g_sorted[s] = make_float2(d0, e0);
    }
    {
        int s = atomicAdd(&g_C[b1], 1);
        g_sorted[s] = make_float2(d1, e1);
    }
    cluster_sync();                                            // B4

    // ---- Phase 4: per-item risk + direct accumulation into out ----
    #pragma unroll
    for (int u = 0; u < 2; ++u) {
        float d  = (u == 0) ? d0  : d1;
        float e_ = (u == 0) ? ev0 : ev1;
        int   b  = (u == 0) ? b0  : b1;
        int s0 = __ldcg(&g_S[b]);
        int s1 = __ldcg(&g_C[b]);          // end after scatter
        float S = __ldcg(&g_W[b]);
        for (int s = s0; s < s1; ++s) {
            float2 v = __ldcg(&g_sorted[s]);
            if (v.x < d) S += v.y;          // strict <: self & ties excluded
        }
        float risk = total - S;             // sum over d_j >= d_i
        acc -= e_ * __logf(risk);
    }
    #pragma unroll
    for (int off = 16; off > 0; off >>= 1)
        acc += __shfl_down_sync(0xFFFFFFFFu, acc, off);
    if (lane == 0) atomicAdd(out, -acc / (float)N);
    // kernel exit flushes atomics; out[0] was zeroed before B1
}

extern "C" void kernel_launch(void* const* d_in, const int* in_sizes, int n_in,
                              void* d_out, int out_size) {
    const float* theta = (const float*)d_in[0];  // hazard_pred (N,1)
    const float* dur   = (const float*)d_in[1];  // durations (N,)
    const float* ev    = (const float*)d_in[2];  // events (N,)
    float* out = (float*)d_out;

    static int configured = 0;
    if (!configured) {
        cudaFuncSetAttribute(cox_cluster_kernel,
                             cudaFuncAttributeMaxDynamicSharedMemorySize,
                             SMEM_BYTES);
        configured = 1;
    }
    cox_cluster_kernel<<<NB, TPB, SMEM_BYTES>>>(theta, dur, ev, out);
}

// round 9
// speedup vs baseline: 1.1954x; 1.0122x over previous
#include <cuda_runtime.h>
#include <cstdint>
#include <math.h>

#define N     16384
#define BKT   8192          // buckets (lambda = 2)
#define NB    8             // CTAs in ONE cluster
#define TPB   1024          // 8192 threads total, 2 items each
#define BPC   (BKT / NB)    // 1024 buckets owned per CTA
#define BPT   (BKT / TPB)   // 8 buckets scanned per thread

// ---- global scratch (L2; zero-initialized at load; re-zeroed each run) ----
__device__ float  g_W[BKT];       // bucket weight histogram (atomic)
__device__ int    g_A[BKT];       // bucket count histogram (atomic)
__device__ int    g_C[BKT];       // scatter cursor (start -> end); overwritten
__device__ float2 g_sorted[N];    // {duration, exp(theta)}; fully overwritten

// dynamic smem: Wp float[BKT] @0 (32KB), S int[BKT] @32768 (32KB)
#define SMEM_BYTES 65536
extern __shared__ char smem_raw[];

__device__ __forceinline__ void cluster_sync() {
    // arrive = release, wait = acquire at cluster scope: no explicit fences
    asm volatile("barrier.cluster.arrive.aligned;" ::: "memory");
    asm volatile("barrier.cluster.wait.aligned;" ::: "memory");
}

__device__ __forceinline__ int bucket_of(float d) {
    int b = (int)(d * (float)BKT);
    if (b >= BKT) b = BKT - 1;
    if (b < 0) b = 0;
    return b;
}

__global__ void __launch_bounds__(TPB, 1) __cluster_dims__(NB, 1, 1)
cox_cluster_kernel(const float* __restrict__ theta,
                   const float* __restrict__ dur,
                   const float* __restrict__ ev,
                   float* __restrict__ out) {
    float* Wp = (float*)(smem_raw);           // full exclusive weight prefix
    int*   S  = (int*)(smem_raw + 32768);     // full bucket starts

    __shared__ float warpTotF[32];
    __shared__ float warpPreF[32];
    __shared__ int   warpTotI[32];
    __shared__ int   warpPreI[32];
    __shared__ float s_total;

    const int t    = threadIdx.x;
    const int k    = blockIdx.x;
    const int g    = k * TPB + t;
    const int lane = t & 31;
    const int wid  = t >> 5;
    const int base = k * BPC;                 // this CTA's owned bucket segment

    // ---- Pass A: direct global histogram (arrays are pre-zeroed) ----
    const int i0 = g;
    const int i1 = g + NB * TPB;
    float th0 = theta[i0], th1 = theta[i1];
    float d0  = dur[i0],   d1  = dur[i1];
    float ev0 = ev[i0],    ev1 = ev[i1];
    float e0  = __expf(th0), e1 = __expf(th1);
    int   b0  = bucket_of(d0), b1 = bucket_of(d1);
    float acc = ev0 * th0 + ev1 * th1;
    atomicAdd(&g_W[b0], e0);  atomicAdd(&g_A[b0], 1);
    atomicAdd(&g_W[b1], e1);  atomicAdd(&g_A[b1], 1);
    if (g == 0) out[0] = 0.0f;                // ordered before adds by B1..B3
    cluster_sync();                                            // B1

    // ---- Scan: EVERY CTA scans all 8192 buckets (redundant, local) ----
    float w[BPT]; int a[BPT];
    float locW[BPT]; int locC[BPT];
    const int b8 = t * BPT;
    float runW = 0.0f; int runC = 0;
    #pragma unroll
    for (int j = 0; j < BPT; ++j) {
        w[j] = __ldcg(&g_W[b8 + j]);
        a[j] = __ldcg(&g_A[b8 + j]);
        locW[j] = runW;  runW += w[j];
        locC[j] = runC;  runC += a[j];
    }
    float iW = runW; int iC = runC;
    #pragma unroll
    for (int off = 1; off < 32; off <<= 1) {
        float uW = __shfl_up_sync(0xFFFFFFFFu, iW, off);
        int   uC = __shfl_up_sync(0xFFFFFFFFu, iC, off);
        if (lane >= off) { iW += uW; iC += uC; }
    }
    if (lane == 31) { warpTotF[wid] = iW; warpTotI[wid] = iC; }
    __syncthreads();
    if (wid == 0) {
        float vF = warpTotF[lane]; int vI = warpTotI[lane];
        float wF = vF; int wI = vI;
        #pragma unroll
        for (int off = 1; off < 32; off <<= 1) {
            float uF = __shfl_up_sync(0xFFFFFFFFu, wF, off);
            int   uI = __shfl_up_sync(0xFFFFFFFFu, wI, off);
            if (lane >= off) { wF += uF; wI += uI; }
        }
        warpPreF[lane] = wF - vF;             // exclusive warp prefix
        warpPreI[lane] = wI - vI;
        if (lane == 31) s_total = wF;
    }
    __syncthreads();
    const float exclW = warpPreF[wid] + (iW - runW);
    const int   exclC = warpPreI[wid] + (iC - runC);
    #pragma unroll
    for (int j = 0; j < BPT; ++j) {
        Wp[b8 + j] = exclW + locW[j];         // smem: exclusive weight prefix
        S[b8 + j]  = exclC + locC[j];         // smem: bucket start
    }
    const float total = s_total;
    __syncthreads();
    // publish global scatter cursors for OWNED segment only (1 store/thread)
    g_C[base + t] = S[base + t];
    cluster_sync();                                            // B2

    // ---- re-zero owned histogram segment for the next graph replay ----
    // (all scan reads of g_W/g_A completed before B2)
    g_W[base + t] = 0.0f;
    g_A[base + t] = 0;

    // ---- Pass B: scatter (d, e) into bucket-grouped array ----
    {
        int s = atomicAdd(&g_C[b0], 1);
        g_sorted[s] = make_float2(d0, e0);
    }
    {
        int s = atomicAdd(&g_C[b1], 1);
        g_sorted[s] = make_float2(d1, e1);
    }
    cluster_sync();                                            // B3

    // ---- Phase 4: per-item risk (prefix/starts from smem, items from L2) ----
    #pragma unroll
    for (int u = 0; u < 2; ++u) {
        float d  = (u == 0) ? d0  : d1;
        float e_ = (u == 0) ? ev0 : ev1;
        int   b  = (u == 0) ? b0  : b1;
        int s0 = S[b];                        // LDS
        int s1 = __ldcg(&g_C[b]);             // end after scatter (L2)
        float Sa = Wp[b];                     // LDS
        for (int s = s0; s < s1; ++s) {
            float2 v = __ldcg(&g_sorted[s]);
            if (v.x < d) Sa += v.y;           // strict <: self & ties excluded
        }
        float risk = total - Sa;              // sum over d_j >= d_i
        acc -= e_ * __logf(risk);
    }
    #pragma unroll
    for (int off = 16; off > 0; off >>= 1)
        acc += __shfl_down_sync(0xFFFFFFFFu, acc, off);
    if (lane == 0) atomicAdd(out, -acc / (float)N);
    // kernel exit flushes atomics; scratch left zeroed for next replay
}

extern "C" void kernel_launch(void* const* d_in, const int* in_sizes, int n_in,
                              void* d_out, int out_size) {
    const float* theta = (const float*)d_in[0];  // hazard_pred (N,1)
    const float* dur   = (const float*)d_in[1];  // durations (N,)
    const float* ev    = (const float*)d_in[2];  // events (N,)
    float* out = (float*)d_out;

    static int configured = 0;
    if (!configured) {
        cudaFuncSetAttribute(cox_cluster_kernel,
                             cudaFuncAttributeMaxDynamicSharedMemorySize,
                             SMEM_BYTES);
        configured = 1;
    }
    cox_cluster_kernel<<<NB, TPB, SMEM_BYTES>>>(theta, dur, ev, out);
}